// round 5
// baseline (speedup 1.0000x reference)
#include <cuda_runtime.h>
#include <math.h>

#define M_PTS   2048
#define N_VOX   65536
#define TPB_B   256
#define GRID_B  (N_VOX / TPB_B)     // 256 blocks
#define NCDIM   10
#define NCELL   (NCDIM * NCDIM * NCDIM)   // 1000 cells, 0.5 pitch, [-2.5, 2.5]^3

__device__ float4 g_sorted[M_PTS];        // points grouped by cell (q-space)
__device__ int    g_cellstart[NCELL + 1];
__device__ float4 g_part[GRID_B];         // {pred_sum, s1, s2, mask_sum}
__device__ unsigned int g_done = 0;       // last-block counter (self-resetting)

// ---------------- Kernel A: matrix + transform + grid build (1 block) ----------------
__global__ __launch_bounds__(512) void build_kernel(
    const float* __restrict__ quat,  const float* __restrict__ tran,
    const float* __restrict__ model, const float* __restrict__ view) {
    __shared__ float Ms[16];
    __shared__ float qx[M_PTS], qy[M_PTS], qz[M_PTS];
    __shared__ short cellof[M_PTS];
    __shared__ int   cnt[1024];      // cell counts (padded to 1024)
    __shared__ int   start[1024];    // exclusive starts
    __shared__ int   cur[NCELL];     // scatter cursors
    __shared__ int   wsum[16], wscan[16];

    const int t = threadIdx.x;
    const int lane = t & 31, w = t >> 5;

    for (int i = t; i < 1024; i += 512) cnt[i] = 0;

    if (t == 0) {
        float q[4]; float s = 0.0f;
#pragma unroll
        for (int i = 0; i < 4; i++) { q[i] = quat[i]; s += q[i] * q[i]; }
        float f = sqrtf(2.0f / s);
#pragma unroll
        for (int i = 0; i < 4; i++) q[i] *= f;
        float Q[4][4];
#pragma unroll
        for (int i = 0; i < 4; i++)
#pragma unroll
            for (int j = 0; j < 4; j++) Q[i][j] = q[i] * q[j];
        float E[4][4] = {
            {1.0f - Q[2][2] - Q[3][3], Q[1][2] - Q[3][0],        Q[1][3] + Q[2][0],        tran[0]},
            {Q[1][2] + Q[3][0],        1.0f - Q[1][1] - Q[3][3], Q[2][3] - Q[1][0],        tran[1]},
            {Q[1][3] - Q[2][0],        Q[2][3] + Q[1][0],        1.0f - Q[1][1] - Q[2][2], tran[2]},
            {0.0f, 0.0f, 0.0f, 1.0f}};
        float A[4][8];
        for (int i = 0; i < 4; i++)
            for (int j = 0; j < 4; j++) {
                A[i][j]     = view[i * 4 + j];
                A[i][j + 4] = (i == j) ? 1.0f : 0.0f;
            }
        for (int col = 0; col < 4; col++) {
            int piv = col; float best = fabsf(A[col][col]);
            for (int r = col + 1; r < 4; r++)
                if (fabsf(A[r][col]) > best) { best = fabsf(A[r][col]); piv = r; }
            if (piv != col)
                for (int j = 0; j < 8; j++) { float tmp = A[col][j]; A[col][j] = A[piv][j]; A[piv][j] = tmp; }
            float d = 1.0f / A[col][col];
            for (int j = 0; j < 8; j++) A[col][j] *= d;
            for (int r = 0; r < 4; r++) {
                if (r == col) continue;
                float m = A[r][col];
                for (int j = 0; j < 8; j++) A[r][j] -= m * A[col][j];
            }
        }
        for (int i = 0; i < 4; i++)
            for (int j = 0; j < 4; j++) {
                float acc = 0.0f;
                for (int k = 0; k < 4; k++) acc += A[i][k + 4] * E[k][j];
                Ms[i * 4 + j] = acc;
            }
    }
    __syncthreads();

    // Transform points to q-space; bin. Points outside [-2.5, 2.5)^3 can never be
    // within 0.25 of a center in [-2,2]^3 -> clamp makes them irrelevant: discard.
    for (int i = t; i < M_PTS; i += 512) {
        float mx = model[3 * i + 0], my = model[3 * i + 1], mz = model[3 * i + 2];
        float hx = Ms[0]  * mx + Ms[1]  * my + Ms[2]  * mz + Ms[3];
        float hy = Ms[4]  * mx + Ms[5]  * my + Ms[6]  * mz + Ms[7];
        float hz = Ms[8]  * mx + Ms[9]  * my + Ms[10] * mz + Ms[11];
        float hw = Ms[12] * mx + Ms[13] * my + Ms[14] * mz + Ms[15];
        float inv = 2.0f / hw;               // pred / RES
        float x = hx * inv, y = hy * inv, z = hz * inv;
        qx[i] = x; qy[i] = y; qz[i] = z;
        int ix = (int)floorf(2.0f * x + 5.0f);
        int iy = (int)floorf(2.0f * y + 5.0f);
        int iz = (int)floorf(2.0f * z + 5.0f);
        short cell = -1;
        if (ix >= 0 && ix < NCDIM && iy >= 0 && iy < NCDIM && iz >= 0 && iz < NCDIM) {
            cell = (short)((ix * NCDIM + iy) * NCDIM + iz);
            atomicAdd(&cnt[cell], 1);
        }
        cellof[i] = cell;
    }
    __syncthreads();

    // Exclusive scan of cnt[0..1023] (pair per thread + warp scans).
    int c0 = cnt[2 * t], c1 = cnt[2 * t + 1];
    int s2 = c0 + c1;
    int incl = s2;
#pragma unroll
    for (int off = 1; off < 32; off <<= 1) {
        int v = __shfl_up_sync(0xffffffffu, incl, off);
        if (lane >= off) incl += v;
    }
    if (lane == 31) wsum[w] = incl;
    __syncthreads();
    if (t < 16) {
        int v = wsum[t];
        int in2 = v;
#pragma unroll
        for (int off = 1; off < 16; off <<= 1) {
            int u = __shfl_up_sync(0x0000ffffu, in2, off);
            if (t >= off) in2 += u;
        }
        wscan[t] = in2;
    }
    __syncthreads();
    int base = (w > 0) ? wscan[w - 1] : 0;
    int excl = base + incl - s2;
    if (2 * t     <= NCELL) start[2 * t]     = excl;
    if (2 * t + 1 <= NCELL) start[2 * t + 1] = excl + c0;
    __syncthreads();

    for (int i = t; i <= NCELL; i += 512) {
        g_cellstart[i] = start[i];
        if (i < NCELL) cur[i] = start[i];
    }
    __syncthreads();

    // Scatter points into cell-grouped global array.
    for (int i = t; i < M_PTS; i += 512) {
        int cell = cellof[i];
        if (cell >= 0) {
            int pos = atomicAdd(&cur[cell], 1);
            g_sorted[pos] = make_float4(qx[i], qy[i], qz[i], 0.0f);
        }
    }
}

// ---------------- Kernel B: per-voxel neighbor query + full reduction ----------------
__global__ __launch_bounds__(TPB_B) void query_kernel(
    const float* __restrict__ centers, const float* __restrict__ freev,
    const float* __restrict__ occo,    const float* __restrict__ masks,
    float* __restrict__ out) {
    __shared__ float red[4][TPB_B / 32];
    __shared__ bool  amLast;

    const int t = threadIdx.x;
    const int v = blockIdx.x * TPB_B + t;

    const float cx = centers[3 * v + 0] * 2.0f;
    const float cy = centers[3 * v + 1] * 2.0f;
    const float cz = centers[3 * v + 2] * 2.0f;
    const float fo = freev[v] + occo[v];
    const float mk = masks[v];

    // Cells overlapping the L-inf 0.25 box around c: indices i0, i0+1 per dim.
    const int ix0 = (int)floorf(2.0f * cx + 4.5f);
    const int iy0 = (int)floorf(2.0f * cy + 4.5f);
    const int iz0 = (int)floorf(2.0f * cz + 4.5f);

    float m = 1e30f;
#pragma unroll
    for (int a = 0; a < 2; a++) {
        int ix = ix0 + a;
        if (ix < 0 || ix >= NCDIM) continue;
#pragma unroll
        for (int b = 0; b < 2; b++) {
            int iy = iy0 + b;
            if (iy < 0 || iy >= NCDIM) continue;
#pragma unroll
            for (int c = 0; c < 2; c++) {
                int iz = iz0 + c;
                if (iz < 0 || iz >= NCDIM) continue;
                int cell = (ix * NCDIM + iy) * NCDIM + iz;
                int s = g_cellstart[cell];
                int e = g_cellstart[cell + 1];
                for (int k = s; k < e; k++) {
                    float4 p = g_sorted[k];
                    float dx = cx - p.x, dy = cy - p.y, dz = cz - p.z;
                    float d2 = fmaf(dx, dx, fmaf(dy, dy, dz * dz));
                    m = fminf(m, d2);
                }
            }
        }
    }

    float d = sqrtf(fmaxf(m, 0.0f));
    d = fminf(d, 0.25f);
    float o = fmaxf(1.0f - 4.0f * d, 0.0f);

    float ps = o, s1 = fo * o, s2 = mk * o, msum = mk;
    const unsigned full = 0xffffffffu;
#pragma unroll
    for (int off = 16; off > 0; off >>= 1) {
        ps   += __shfl_down_sync(full, ps, off);
        s1   += __shfl_down_sync(full, s1, off);
        s2   += __shfl_down_sync(full, s2, off);
        msum += __shfl_down_sync(full, msum, off);
    }
    int lane = t & 31, w = t >> 5;
    if (lane == 0) { red[0][w] = ps; red[1][w] = s1; red[2][w] = s2; red[3][w] = msum; }
    __syncthreads();
    if (t == 0) {
        float tps = 0.f, ts1 = 0.f, ts2 = 0.f, tms = 0.f;
#pragma unroll
        for (int i = 0; i < TPB_B / 32; i++) {
            tps += red[0][i]; ts1 += red[1][i]; ts2 += red[2][i]; tms += red[3][i];
        }
        g_part[blockIdx.x] = make_float4(tps, ts1, ts2, tms);
        __threadfence();
        unsigned r = atomicAdd(&g_done, 1u);
        amLast = (r == GRID_B - 1);
    }
    __syncthreads();

    // Last finished block folds all partials and writes the scalar output.
    if (amLast) {
        float4 p = __ldcg(&g_part[t]);      // t in [0, 256) == GRID_B
#pragma unroll
        for (int off = 16; off > 0; off >>= 1) {
            p.x += __shfl_down_sync(full, p.x, off);
            p.y += __shfl_down_sync(full, p.y, off);
            p.z += __shfl_down_sync(full, p.z, off);
            p.w += __shfl_down_sync(full, p.w, off);
        }
        if (lane == 0) { red[0][w] = p.x; red[1][w] = p.y; red[2][w] = p.z; red[3][w] = p.w; }
        __syncthreads();
        if (t == 0) {
            double ps2 = 0.0, s12 = 0.0, s22 = 0.0, ms2 = 0.0;
#pragma unroll
            for (int i = 0; i < TPB_B / 32; i++) {
                ps2 += (double)red[0][i]; s12 += (double)red[1][i];
                s22 += (double)red[2][i]; ms2 += (double)red[3][i];
            }
            double t1 = (ps2 > 0.0) ? s12 / ps2 : 0.0;
            double t2 = (ms2 > 0.0) ? s22 / ms2 : 0.0;
            out[0] = (float)(t1 - t2);
            g_done = 0;   // reset for next graph replay
        }
    }
}

extern "C" void kernel_launch(void* const* d_in, const int* in_sizes, int n_in,
                              void* d_out, int out_size) {
    const float* quat    = (const float*)d_in[0];
    const float* tran    = (const float*)d_in[1];
    const float* model   = (const float*)d_in[2];
    const float* view    = (const float*)d_in[3];
    const float* centers = (const float*)d_in[4];
    const float* freev   = (const float*)d_in[5];
    const float* occo    = (const float*)d_in[6];
    const float* masks   = (const float*)d_in[7];
    (void)in_sizes; (void)n_in; (void)out_size;

    build_kernel<<<1, 512>>>(quat, tran, model, view);
    query_kernel<<<GRID_B, TPB_B>>>(centers, freev, occo, masks, (float*)d_out);
}